// round 1
// baseline (speedup 1.0000x reference)
#include <cuda_runtime.h>

#define NN   100000
#define NE   3200000
#define FIN  512
#define HIDN 64
#define NC   16

// ---------------- scratch (static device globals; no allocs) ----------------
__device__ float g_h1[NN * HIDN];     // x @ W1^T
__device__ float g_hr[NN * HIDN];     // aggregated + bias + relu
__device__ float g_h2[NN * NC];       // hr @ W2^T
__device__ float g_deg[NN];
__device__ float g_dinv[NN];
__device__ int   g_cnt[NN];
__device__ int   g_ptr[NN + 1];
__device__ int   g_wptr[NN];
__device__ int   g_srow[NE];          // CSR (grouped by target): source node
__device__ float g_norm[NE];          // CSR: edge norm = dinv[src]*w*dinv[dst]

static inline int cdiv(int a, int b) { return (a + b - 1) / b; }

// ---------------- 0: init deg (self-loop weight 1.0) and counters -----------
__global__ void init_nodes_kernel() {
    int i = blockIdx.x * blockDim.x + threadIdx.x;
    if (i < NN) { g_deg[i] = 1.0f; g_cnt[i] = 0; }
}

// ---------------- 1: degree + histogram over edges ---------------------------
__global__ void edge_pass1_kernel(const int* __restrict__ ei,
                                  const float* __restrict__ ea) {
    int e = blockIdx.x * blockDim.x + threadIdx.x;
    if (e >= NE) return;
    int dst = ei[NE + e];
    atomicAdd(&g_deg[dst], ea[e]);
    atomicAdd(&g_cnt[dst], 1);
}

// ---------------- 2: dinv = rsqrt(deg)  (deg >= 1 always) -------------------
__global__ void dinv_kernel() {
    int i = blockIdx.x * blockDim.x + threadIdx.x;
    if (i < NN) g_dinv[i] = rsqrtf(g_deg[i]);
}

// ---------------- 3: exclusive scan of g_cnt -> g_ptr, g_wptr ----------------
__global__ void scan_kernel() {
    __shared__ int ssum[1024];
    const int t  = threadIdx.x;
    const int CH = (NN + 1023) / 1024;          // 98
    int beg = t * CH;
    int end = beg + CH; if (end > NN) end = NN;
    int s = 0;
    for (int i = beg; i < end; i++) s += g_cnt[i];
    ssum[t] = s;
    __syncthreads();
    // Hillis-Steele inclusive scan
    for (int off = 1; off < 1024; off <<= 1) {
        int v = (t >= off) ? ssum[t - off] : 0;
        __syncthreads();
        if (t >= off) ssum[t] += v;
        __syncthreads();
    }
    int run = (t == 0) ? 0 : ssum[t - 1];
    for (int i = beg; i < end; i++) {
        g_ptr[i]  = run;
        g_wptr[i] = run;
        run += g_cnt[i];
    }
    if (t == 1023) g_ptr[NN] = run;             // == NE
}

// ---------------- 4: scatter edges into CSR ---------------------------------
__global__ void edge_fill_kernel(const int* __restrict__ ei,
                                 const float* __restrict__ ea) {
    int e = blockIdx.x * blockDim.x + threadIdx.x;
    if (e >= NE) return;
    int src = ei[e];
    int dst = ei[NE + e];
    float nrm = g_dinv[src] * ea[e] * g_dinv[dst];
    int pos = atomicAdd(&g_wptr[dst], 1);
    g_srow[pos] = src;
    g_norm[pos] = nrm;
}

// ---------------- 5: GEMM1  h1 = x @ W1^T  (M=1e5, K=512, N=64) -------------
// 128x64 block tile, BK=32, 256 threads, 8x4 per-thread microtile.
__global__ void __launch_bounds__(256) gemm1_kernel(const float* __restrict__ x,
                                                    const float* __restrict__ W1) {
    __shared__ float xs[32][132];   // [k][m], padded (row stride 528B, 16B-aligned)
    __shared__ float ws[32][64];    // [k][n]
    const int bm  = blockIdx.x * 128;
    const int tid = threadIdx.x;
    const int tx  = tid & 15;       // col group (4 cols)
    const int ty  = tid >> 4;       // row group (8 rows)

    float acc[8][4];
#pragma unroll
    for (int r = 0; r < 8; r++)
#pragma unroll
        for (int c = 0; c < 4; c++) acc[r][c] = 0.0f;

    for (int k0 = 0; k0 < FIN; k0 += 32) {
        // load x tile (128 rows x 32 k), transposed into xs[k][m]
#pragma unroll
        for (int i = 0; i < 4; i++) {
            int idx = tid + i * 256;          // 0..1023 float4 slots
            int r   = idx >> 3;               // row in tile
            int c4  = idx & 7;                // float4 within row
            int gr  = bm + r;
            float4 v = make_float4(0.f, 0.f, 0.f, 0.f);
            if (gr < NN)
                v = *(const float4*)(x + (size_t)gr * FIN + k0 + c4 * 4);
            xs[c4 * 4 + 0][r] = v.x;
            xs[c4 * 4 + 1][r] = v.y;
            xs[c4 * 4 + 2][r] = v.z;
            xs[c4 * 4 + 3][r] = v.w;
        }
        // load W tile: ws[kk][n] = W1[n*512 + k0+kk]
#pragma unroll
        for (int i = 0; i < 2; i++) {
            int idx = tid + i * 256;          // 0..511 float4 slots
            int n   = idx >> 3;
            int c4  = idx & 7;
            float4 v = *(const float4*)(W1 + (size_t)n * FIN + k0 + c4 * 4);
            ws[c4 * 4 + 0][n] = v.x;
            ws[c4 * 4 + 1][n] = v.y;
            ws[c4 * 4 + 2][n] = v.z;
            ws[c4 * 4 + 3][n] = v.w;
        }
        __syncthreads();
#pragma unroll
        for (int kk = 0; kk < 32; kk++) {
            float a[8], b[4];
            *(float4*)&a[0] = *(const float4*)&xs[kk][ty * 8];
            *(float4*)&a[4] = *(const float4*)&xs[kk][ty * 8 + 4];
            *(float4*)&b[0] = *(const float4*)&ws[kk][tx * 4];
#pragma unroll
            for (int r = 0; r < 8; r++)
#pragma unroll
                for (int c = 0; c < 4; c++)
                    acc[r][c] = fmaf(a[r], b[c], acc[r][c]);
        }
        __syncthreads();
    }
#pragma unroll
    for (int r = 0; r < 8; r++) {
        int gr = bm + ty * 8 + r;
        if (gr < NN)
            ((float4*)g_h1)[(size_t)gr * 16 + tx] =
                make_float4(acc[r][0], acc[r][1], acc[r][2], acc[r][3]);
    }
}

// ---------------- 6: aggregate layer 1 + bias + relu ------------------------
// 16 lanes per node (float4 each = 64 feats), 16 nodes per 256-thread block.
__global__ void __launch_bounds__(256) agg1_kernel(const float* __restrict__ b1) {
    int g = blockIdx.x * 16 + (threadIdx.x >> 4);
    int l = threadIdx.x & 15;
    if (g >= NN) return;

    const float4* h1v = (const float4*)g_h1;
    float di = g_dinv[g];
    float sl = di * di;                         // self-loop norm
    float4 acc = h1v[(size_t)g * 16 + l];
    acc.x *= sl; acc.y *= sl; acc.z *= sl; acc.w *= sl;

    int e   = g_ptr[g];
    int end = g_ptr[g + 1];
    for (; e + 4 <= end; e += 4) {
        int   s0 = g_srow[e],     s1 = g_srow[e + 1],
              s2 = g_srow[e + 2], s3 = g_srow[e + 3];
        float n0 = g_norm[e],     n1 = g_norm[e + 1],
              n2 = g_norm[e + 2], n3 = g_norm[e + 3];
        float4 v0 = h1v[(size_t)s0 * 16 + l];
        float4 v1 = h1v[(size_t)s1 * 16 + l];
        float4 v2 = h1v[(size_t)s2 * 16 + l];
        float4 v3 = h1v[(size_t)s3 * 16 + l];
        acc.x += v0.x*n0 + v1.x*n1 + v2.x*n2 + v3.x*n3;
        acc.y += v0.y*n0 + v1.y*n1 + v2.y*n2 + v3.y*n3;
        acc.z += v0.z*n0 + v1.z*n1 + v2.z*n2 + v3.z*n3;
        acc.w += v0.w*n0 + v1.w*n1 + v2.w*n2 + v3.w*n3;
    }
    for (; e < end; e++) {
        int   s = g_srow[e];
        float n = g_norm[e];
        float4 v = h1v[(size_t)s * 16 + l];
        acc.x += v.x * n; acc.y += v.y * n;
        acc.z += v.z * n; acc.w += v.w * n;
    }
    float4 b = ((const float4*)b1)[l];
    acc.x = fmaxf(acc.x + b.x, 0.f);
    acc.y = fmaxf(acc.y + b.y, 0.f);
    acc.z = fmaxf(acc.z + b.z, 0.f);
    acc.w = fmaxf(acc.w + b.w, 0.f);
    ((float4*)g_hr)[(size_t)g * 16 + l] = acc;
}

// ---------------- 7: GEMM2  h2 = hr @ W2^T  (64 nodes / block) --------------
__global__ void __launch_bounds__(256) gemm2_kernel(const float* __restrict__ W2) {
    __shared__ float hs[64][65];
    __shared__ float ws[16][65];
    const int node0 = blockIdx.x * 64;
    const int t = threadIdx.x;

#pragma unroll
    for (int i = 0; i < 4; i++) {
        int idx = t + i * 256;                  // 0..1023 float4 slots
        int r   = idx >> 4;                     // node row
        int c4  = idx & 15;
        float4 v = make_float4(0.f, 0.f, 0.f, 0.f);
        if (node0 + r < NN)
            v = ((const float4*)g_hr)[(size_t)(node0 + r) * 16 + c4];
        hs[r][c4 * 4 + 0] = v.x; hs[r][c4 * 4 + 1] = v.y;
        hs[r][c4 * 4 + 2] = v.z; hs[r][c4 * 4 + 3] = v.w;
    }
    {
        int idx = t;                            // 256 float4 = all of W2
        int n   = idx >> 4;
        int c4  = idx & 15;
        float4 v = *(const float4*)(W2 + (size_t)n * HIDN + c4 * 4);
        ws[n][c4 * 4 + 0] = v.x; ws[n][c4 * 4 + 1] = v.y;
        ws[n][c4 * 4 + 2] = v.z; ws[n][c4 * 4 + 3] = v.w;
    }
    __syncthreads();

    int n  = t >> 2;
    int cg = t & 3;
    float a0 = 0.f, a1 = 0.f, a2 = 0.f, a3 = 0.f;
#pragma unroll
    for (int k = 0; k < HIDN; k++) {
        float h = hs[n][k];
        a0 = fmaf(h, ws[cg * 4 + 0][k], a0);
        a1 = fmaf(h, ws[cg * 4 + 1][k], a1);
        a2 = fmaf(h, ws[cg * 4 + 2][k], a2);
        a3 = fmaf(h, ws[cg * 4 + 3][k], a3);
    }
    if (node0 + n < NN)
        ((float4*)g_h2)[(size_t)(node0 + n) * 4 + cg] = make_float4(a0, a1, a2, a3);
}

// ---------------- 8: aggregate layer 2 + bias + log_softmax -----------------
// 4 lanes per node (float4 each = 16 classes), 64 nodes per block.
__global__ void __launch_bounds__(256) agg2_kernel(const float* __restrict__ b2,
                                                   float* __restrict__ out) {
    int g = blockIdx.x * 64 + (threadIdx.x >> 2);
    int l = threadIdx.x & 3;
    bool valid = (g < NN);
    if (!valid) g = 0;                          // keep whole warp alive for shfl

    const float4* h2v = (const float4*)g_h2;
    float di = g_dinv[g];
    float sl = di * di;
    float4 acc = h2v[(size_t)g * 4 + l];
    acc.x *= sl; acc.y *= sl; acc.z *= sl; acc.w *= sl;

    int e   = g_ptr[g];
    int end = g_ptr[g + 1];
    for (; e + 4 <= end; e += 4) {
        int   s0 = g_srow[e],     s1 = g_srow[e + 1],
              s2 = g_srow[e + 2], s3 = g_srow[e + 3];
        float n0 = g_norm[e],     n1 = g_norm[e + 1],
              n2 = g_norm[e + 2], n3 = g_norm[e + 3];
        float4 v0 = h2v[(size_t)s0 * 4 + l];
        float4 v1 = h2v[(size_t)s1 * 4 + l];
        float4 v2 = h2v[(size_t)s2 * 4 + l];
        float4 v3 = h2v[(size_t)s3 * 4 + l];
        acc.x += v0.x*n0 + v1.x*n1 + v2.x*n2 + v3.x*n3;
        acc.y += v0.y*n0 + v1.y*n1 + v2.y*n2 + v3.y*n3;
        acc.z += v0.z*n0 + v1.z*n1 + v2.z*n2 + v3.z*n3;
        acc.w += v0.w*n0 + v1.w*n1 + v2.w*n2 + v3.w*n3;
    }
    for (; e < end; e++) {
        int   s = g_srow[e];
        float n = g_norm[e];
        float4 v = h2v[(size_t)s * 4 + l];
        acc.x += v.x * n; acc.y += v.y * n;
        acc.z += v.z * n; acc.w += v.w * n;
    }
    float4 b = ((const float4*)b2)[l];
    acc.x += b.x; acc.y += b.y; acc.z += b.z; acc.w += b.w;

    // log_softmax across 16 values held by 4 lanes
    float m = fmaxf(fmaxf(acc.x, acc.y), fmaxf(acc.z, acc.w));
    m = fmaxf(m, __shfl_xor_sync(0xffffffffu, m, 1));
    m = fmaxf(m, __shfl_xor_sync(0xffffffffu, m, 2));
    float s = __expf(acc.x - m) + __expf(acc.y - m) +
              __expf(acc.z - m) + __expf(acc.w - m);
    s += __shfl_xor_sync(0xffffffffu, s, 1);
    s += __shfl_xor_sync(0xffffffffu, s, 2);
    float lse = m + __logf(s);
    acc.x -= lse; acc.y -= lse; acc.z -= lse; acc.w -= lse;

    if (valid)
        ((float4*)out)[(size_t)g * 4 + l] = acc;
}

// ---------------- launch ----------------------------------------------------
extern "C" void kernel_launch(void* const* d_in, const int* in_sizes, int n_in,
                              void* d_out, int out_size) {
    const float* x  = (const float*)d_in[0];
    const int*   ei = (const int*)  d_in[1];
    const float* ea = (const float*)d_in[2];
    const float* W1 = (const float*)d_in[3];
    const float* b1 = (const float*)d_in[4];
    const float* W2 = (const float*)d_in[5];
    const float* b2 = (const float*)d_in[6];
    float* out = (float*)d_out;

    init_nodes_kernel<<<cdiv(NN, 256), 256>>>();
    edge_pass1_kernel<<<cdiv(NE, 256), 256>>>(ei, ea);
    dinv_kernel<<<cdiv(NN, 256), 256>>>();
    scan_kernel<<<1, 1024>>>();
    edge_fill_kernel<<<cdiv(NE, 256), 256>>>(ei, ea);
    gemm1_kernel<<<cdiv(NN, 128), 256>>>(x, W1);
    agg1_kernel<<<cdiv(NN, 16), 256>>>(b1);
    gemm2_kernel<<<cdiv(NN, 64), 256>>>(W2);
    agg2_kernel<<<cdiv(NN, 64), 256>>>(b2, out);
}

// round 2
// speedup vs baseline: 1.3520x; 1.3520x over previous
#include <cuda_runtime.h>

#define NN   100000
#define NE   3200000
#define FIN  512
#define HIDN 64
#define NC   16

#define SCAN_CHUNK 1024
#define NB ((NN + SCAN_CHUNK - 1) / SCAN_CHUNK)   // 98 blocks

// ---------------- scratch (static device globals; no allocs) ----------------
__device__ float g_h1[NN * HIDN];     // x @ W1^T
__device__ float g_hr[NN * HIDN];     // aggregated + bias + relu
__device__ float g_h2[NN * NC];       // hr @ W2^T
__device__ float g_deg[NN];
__device__ float g_dinv[NN];
__device__ int   g_cnt[NN];
__device__ int   g_ptr[NN + 1];
__device__ int   g_wptr[NN];
__device__ int   g_bsum[NB];
__device__ int   g_srow[NE];          // CSR (grouped by target): source node
__device__ float g_norm[NE];          // CSR: edge norm = dinv[src]*w*dinv[dst]

static inline int cdiv(int a, int b) { return (a + b - 1) / b; }

// ---------------- 0: init deg (self-loop weight 1.0) and counters -----------
__global__ void init_nodes_kernel() {
    int i = blockIdx.x * blockDim.x + threadIdx.x;
    if (i < NN) { g_deg[i] = 1.0f; g_cnt[i] = 0; }
}

// ---------------- 1: degree + histogram over edges ---------------------------
__global__ void edge_pass1_kernel(const int* __restrict__ ei,
                                  const float* __restrict__ ea) {
    int e = blockIdx.x * blockDim.x + threadIdx.x;
    if (e >= NE) return;
    int dst = ei[NE + e];
    atomicAdd(&g_deg[dst], ea[e]);
    atomicAdd(&g_cnt[dst], 1);
}

// ---------------- 2: dinv = rsqrt(deg)  (deg >= 1 always) -------------------
__global__ void dinv_kernel() {
    int i = blockIdx.x * blockDim.x + threadIdx.x;
    if (i < NN) g_dinv[i] = rsqrtf(g_deg[i]);
}

// ---------------- 3: multi-block exclusive scan of g_cnt -> g_ptr, g_wptr ----
// Phase A: per-block sums (each block covers 1024 counts with 256 threads)
__global__ void __launch_bounds__(256) scan_a_kernel() {
    __shared__ int red[256];
    const int base = blockIdx.x * SCAN_CHUNK;
    const int t = threadIdx.x;
    int s = 0;
#pragma unroll
    for (int i = 0; i < 4; i++) {
        int idx = base + t * 4 + i;
        if (idx < NN) s += g_cnt[idx];
    }
    red[t] = s;
    __syncthreads();
#pragma unroll
    for (int off = 128; off > 0; off >>= 1) {
        if (t < off) red[t] += red[t + off];
        __syncthreads();
    }
    if (t == 0) g_bsum[blockIdx.x] = red[0];
}

// Phase B: exclusive scan of the 98 block sums (one small block)
__global__ void scan_b_kernel() {
    __shared__ int sh[128];
    const int t = threadIdx.x;                // 128 threads
    int v = (t < NB) ? g_bsum[t] : 0;
    sh[t] = v;
    __syncthreads();
#pragma unroll
    for (int off = 1; off < 128; off <<= 1) {
        int u = (t >= off) ? sh[t - off] : 0;
        __syncthreads();
        sh[t] += u;
        __syncthreads();
    }
    if (t < NB) g_bsum[t] = (t == 0) ? 0 : sh[t - 1];
    if (t == 0) g_ptr[NN] = NE;               // total is statically NE
}

// Phase C: local exclusive scan + block offset -> g_ptr, g_wptr
__global__ void __launch_bounds__(256) scan_c_kernel() {
    __shared__ int sh[256];
    const int base = blockIdx.x * SCAN_CHUNK;
    const int t = threadIdx.x;
    int c[4]; int s = 0;
#pragma unroll
    for (int i = 0; i < 4; i++) {
        int idx = base + t * 4 + i;
        c[i] = (idx < NN) ? g_cnt[idx] : 0;
        s += c[i];
    }
    sh[t] = s;
    __syncthreads();
#pragma unroll
    for (int off = 1; off < 256; off <<= 1) {
        int u = (t >= off) ? sh[t - off] : 0;
        __syncthreads();
        sh[t] += u;
        __syncthreads();
    }
    int run = g_bsum[blockIdx.x] + ((t == 0) ? 0 : sh[t - 1]);
#pragma unroll
    for (int i = 0; i < 4; i++) {
        int idx = base + t * 4 + i;
        if (idx < NN) { g_ptr[idx] = run; g_wptr[idx] = run; run += c[i]; }
    }
}

// ---------------- 4: scatter edges into CSR ---------------------------------
__global__ void edge_fill_kernel(const int* __restrict__ ei,
                                 const float* __restrict__ ea) {
    int e = blockIdx.x * blockDim.x + threadIdx.x;
    if (e >= NE) return;
    int src = ei[e];
    int dst = ei[NE + e];
    float nrm = g_dinv[src] * ea[e] * g_dinv[dst];
    int pos = atomicAdd(&g_wptr[dst], 1);
    g_srow[pos] = src;
    g_norm[pos] = nrm;
}

// ---------------- 5: GEMM1  h1 = x @ W1^T  (M=1e5, K=512, N=64) -------------
// 128x64 block tile, BK=32, 256 threads, 8x4 per-thread microtile.
__global__ void __launch_bounds__(256) gemm1_kernel(const float* __restrict__ x,
                                                    const float* __restrict__ W1) {
    __shared__ float xs[32][132];   // [k][m], padded (row stride 528B, 16B-aligned)
    __shared__ float ws[32][64];    // [k][n]
    const int bm  = blockIdx.x * 128;
    const int tid = threadIdx.x;
    const int tx  = tid & 15;       // col group (4 cols)
    const int ty  = tid >> 4;       // row group (8 rows)

    float acc[8][4];
#pragma unroll
    for (int r = 0; r < 8; r++)
#pragma unroll
        for (int c = 0; c < 4; c++) acc[r][c] = 0.0f;

    for (int k0 = 0; k0 < FIN; k0 += 32) {
        // load x tile (128 rows x 32 k), transposed into xs[k][m]
#pragma unroll
        for (int i = 0; i < 4; i++) {
            int idx = tid + i * 256;          // 0..1023 float4 slots
            int r   = idx >> 3;               // row in tile
            int c4  = idx & 7;                // float4 within row
            int gr  = bm + r;
            float4 v = make_float4(0.f, 0.f, 0.f, 0.f);
            if (gr < NN)
                v = *(const float4*)(x + (size_t)gr * FIN + k0 + c4 * 4);
            xs[c4 * 4 + 0][r] = v.x;
            xs[c4 * 4 + 1][r] = v.y;
            xs[c4 * 4 + 2][r] = v.z;
            xs[c4 * 4 + 3][r] = v.w;
        }
        // load W tile: ws[kk][n] = W1[n*512 + k0+kk]
#pragma unroll
        for (int i = 0; i < 2; i++) {
            int idx = tid + i * 256;          // 0..511 float4 slots
            int n   = idx >> 3;
            int c4  = idx & 7;
            float4 v = *(const float4*)(W1 + (size_t)n * FIN + k0 + c4 * 4);
            ws[c4 * 4 + 0][n] = v.x;
            ws[c4 * 4 + 1][n] = v.y;
            ws[c4 * 4 + 2][n] = v.z;
            ws[c4 * 4 + 3][n] = v.w;
        }
        __syncthreads();
#pragma unroll
        for (int kk = 0; kk < 32; kk++) {
            float a[8], b[4];
            *(float4*)&a[0] = *(const float4*)&xs[kk][ty * 8];
            *(float4*)&a[4] = *(const float4*)&xs[kk][ty * 8 + 4];
            *(float4*)&b[0] = *(const float4*)&ws[kk][tx * 4];
#pragma unroll
            for (int r = 0; r < 8; r++)
#pragma unroll
                for (int c = 0; c < 4; c++)
                    acc[r][c] = fmaf(a[r], b[c], acc[r][c]);
        }
        __syncthreads();
    }
#pragma unroll
    for (int r = 0; r < 8; r++) {
        int gr = bm + ty * 8 + r;
        if (gr < NN)
            ((float4*)g_h1)[(size_t)gr * 16 + tx] =
                make_float4(acc[r][0], acc[r][1], acc[r][2], acc[r][3]);
    }
}

// ---------------- 6: aggregate layer 1 + bias + relu ------------------------
// 16 lanes per node (float4 each = 64 feats), 16 nodes per 256-thread block.
__global__ void __launch_bounds__(256) agg1_kernel(const float* __restrict__ b1) {
    int g = blockIdx.x * 16 + (threadIdx.x >> 4);
    int l = threadIdx.x & 15;
    if (g >= NN) return;

    const float4* h1v = (const float4*)g_h1;
    float di = g_dinv[g];
    float sl = di * di;                         // self-loop norm
    float4 acc = h1v[(size_t)g * 16 + l];
    acc.x *= sl; acc.y *= sl; acc.z *= sl; acc.w *= sl;

    int e   = g_ptr[g];
    int end = g_ptr[g + 1];
    for (; e + 4 <= end; e += 4) {
        int   s0 = g_srow[e],     s1 = g_srow[e + 1],
              s2 = g_srow[e + 2], s3 = g_srow[e + 3];
        float n0 = g_norm[e],     n1 = g_norm[e + 1],
              n2 = g_norm[e + 2], n3 = g_norm[e + 3];
        float4 v0 = h1v[(size_t)s0 * 16 + l];
        float4 v1 = h1v[(size_t)s1 * 16 + l];
        float4 v2 = h1v[(size_t)s2 * 16 + l];
        float4 v3 = h1v[(size_t)s3 * 16 + l];
        acc.x += v0.x*n0 + v1.x*n1 + v2.x*n2 + v3.x*n3;
        acc.y += v0.y*n0 + v1.y*n1 + v2.y*n2 + v3.y*n3;
        acc.z += v0.z*n0 + v1.z*n1 + v2.z*n2 + v3.z*n3;
        acc.w += v0.w*n0 + v1.w*n1 + v2.w*n2 + v3.w*n3;
    }
    for (; e < end; e++) {
        int   s = g_srow[e];
        float n = g_norm[e];
        float4 v = h1v[(size_t)s * 16 + l];
        acc.x += v.x * n; acc.y += v.y * n;
        acc.z += v.z * n; acc.w += v.w * n;
    }
    float4 b = ((const float4*)b1)[l];
    acc.x = fmaxf(acc.x + b.x, 0.f);
    acc.y = fmaxf(acc.y + b.y, 0.f);
    acc.z = fmaxf(acc.z + b.z, 0.f);
    acc.w = fmaxf(acc.w + b.w, 0.f);
    ((float4*)g_hr)[(size_t)g * 16 + l] = acc;
}

// ---------------- 7: GEMM2  h2 = hr @ W2^T  (64 nodes / block) --------------
__global__ void __launch_bounds__(256) gemm2_kernel(const float* __restrict__ W2) {
    __shared__ float hs[64][65];
    __shared__ float ws[16][65];
    const int node0 = blockIdx.x * 64;
    const int t = threadIdx.x;

#pragma unroll
    for (int i = 0; i < 4; i++) {
        int idx = t + i * 256;                  // 0..1023 float4 slots
        int r   = idx >> 4;                     // node row
        int c4  = idx & 15;
        float4 v = make_float4(0.f, 0.f, 0.f, 0.f);
        if (node0 + r < NN)
            v = ((const float4*)g_hr)[(size_t)(node0 + r) * 16 + c4];
        hs[r][c4 * 4 + 0] = v.x; hs[r][c4 * 4 + 1] = v.y;
        hs[r][c4 * 4 + 2] = v.z; hs[r][c4 * 4 + 3] = v.w;
    }
    {
        int idx = t;                            // 256 float4 = all of W2
        int n   = idx >> 4;
        int c4  = idx & 15;
        float4 v = *(const float4*)(W2 + (size_t)n * HIDN + c4 * 4);
        ws[n][c4 * 4 + 0] = v.x; ws[n][c4 * 4 + 1] = v.y;
        ws[n][c4 * 4 + 2] = v.z; ws[n][c4 * 4 + 3] = v.w;
    }
    __syncthreads();

    int n  = t >> 2;
    int cg = t & 3;
    float a0 = 0.f, a1 = 0.f, a2 = 0.f, a3 = 0.f;
#pragma unroll
    for (int k = 0; k < HIDN; k++) {
        float h = hs[n][k];
        a0 = fmaf(h, ws[cg * 4 + 0][k], a0);
        a1 = fmaf(h, ws[cg * 4 + 1][k], a1);
        a2 = fmaf(h, ws[cg * 4 + 2][k], a2);
        a3 = fmaf(h, ws[cg * 4 + 3][k], a3);
    }
    if (node0 + n < NN)
        ((float4*)g_h2)[(size_t)(node0 + n) * 4 + cg] = make_float4(a0, a1, a2, a3);
}

// ---------------- 8: aggregate layer 2 + bias + log_softmax -----------------
// 4 lanes per node (float4 each = 16 classes), 64 nodes per block.
__global__ void __launch_bounds__(256) agg2_kernel(const float* __restrict__ b2,
                                                   float* __restrict__ out) {
    int g = blockIdx.x * 64 + (threadIdx.x >> 2);
    int l = threadIdx.x & 3;
    bool valid = (g < NN);
    if (!valid) g = 0;                          // keep whole warp alive for shfl

    const float4* h2v = (const float4*)g_h2;
    float di = g_dinv[g];
    float sl = di * di;
    float4 acc = h2v[(size_t)g * 4 + l];
    acc.x *= sl; acc.y *= sl; acc.z *= sl; acc.w *= sl;

    int e   = g_ptr[g];
    int end = g_ptr[g + 1];
    for (; e + 4 <= end; e += 4) {
        int   s0 = g_srow[e],     s1 = g_srow[e + 1],
              s2 = g_srow[e + 2], s3 = g_srow[e + 3];
        float n0 = g_norm[e],     n1 = g_norm[e + 1],
              n2 = g_norm[e + 2], n3 = g_norm[e + 3];
        float4 v0 = h2v[(size_t)s0 * 4 + l];
        float4 v1 = h2v[(size_t)s1 * 4 + l];
        float4 v2 = h2v[(size_t)s2 * 4 + l];
        float4 v3 = h2v[(size_t)s3 * 4 + l];
        acc.x += v0.x*n0 + v1.x*n1 + v2.x*n2 + v3.x*n3;
        acc.y += v0.y*n0 + v1.y*n1 + v2.y*n2 + v3.y*n3;
        acc.z += v0.z*n0 + v1.z*n1 + v2.z*n2 + v3.z*n3;
        acc.w += v0.w*n0 + v1.w*n1 + v2.w*n2 + v3.w*n3;
    }
    for (; e < end; e++) {
        int   s = g_srow[e];
        float n = g_norm[e];
        float4 v = h2v[(size_t)s * 4 + l];
        acc.x += v.x * n; acc.y += v.y * n;
        acc.z += v.z * n; acc.w += v.w * n;
    }
    float4 b = ((const float4*)b2)[l];
    acc.x += b.x; acc.y += b.y; acc.z += b.z; acc.w += b.w;

    // log_softmax across 16 values held by 4 lanes
    float m = fmaxf(fmaxf(acc.x, acc.y), fmaxf(acc.z, acc.w));
    m = fmaxf(m, __shfl_xor_sync(0xffffffffu, m, 1));
    m = fmaxf(m, __shfl_xor_sync(0xffffffffu, m, 2));
    float s = __expf(acc.x - m) + __expf(acc.y - m) +
              __expf(acc.z - m) + __expf(acc.w - m);
    s += __shfl_xor_sync(0xffffffffu, s, 1);
    s += __shfl_xor_sync(0xffffffffu, s, 2);
    float lse = m + __logf(s);
    acc.x -= lse; acc.y -= lse; acc.z -= lse; acc.w -= lse;

    if (valid)
        ((float4*)out)[(size_t)g * 4 + l] = acc;
}

// ---------------- launch ----------------------------------------------------
extern "C" void kernel_launch(void* const* d_in, const int* in_sizes, int n_in,
                              void* d_out, int out_size) {
    const float* x  = (const float*)d_in[0];
    const int*   ei = (const int*)  d_in[1];
    const float* ea = (const float*)d_in[2];
    const float* W1 = (const float*)d_in[3];
    const float* b1 = (const float*)d_in[4];
    const float* W2 = (const float*)d_in[5];
    const float* b2 = (const float*)d_in[6];
    float* out = (float*)d_out;

    init_nodes_kernel<<<cdiv(NN, 256), 256>>>();
    edge_pass1_kernel<<<cdiv(NE, 256), 256>>>(ei, ea);
    dinv_kernel<<<cdiv(NN, 256), 256>>>();
    scan_a_kernel<<<NB, 256>>>();
    scan_b_kernel<<<1, 128>>>();
    scan_c_kernel<<<NB, 256>>>();
    edge_fill_kernel<<<cdiv(NE, 256), 256>>>(ei, ea);
    gemm1_kernel<<<cdiv(NN, 128), 256>>>(x, W1);
    agg1_kernel<<<cdiv(NN, 16), 256>>>(b1);
    gemm2_kernel<<<cdiv(NN, 64), 256>>>(W2);
    agg2_kernel<<<cdiv(NN, 64), 256>>>(b2, out);
}